// round 3
// baseline (speedup 1.0000x reference)
#include <cuda_runtime.h>
#include <cuda_bf16.h>
#include <cstdint>

#define NTOK 4096
#define DIM  1024
#define HDIM 4096
#define NE   8

#define TM 128
#define TN 128
#define TK 32

__device__ int   g_counts[NE];
__device__ int   g_tlist[NE * NTOK];
__device__ float g_h[(size_t)NTOK * HDIM];   // relu(x@fc)^2 scratch, 64 MB

// ---------------- helpers ----------------
__device__ __forceinline__ uint32_t smem_u32(const void* p) {
    uint32_t a;
    asm("{ .reg .u64 t; cvta.to.shared.u64 t, %1; cvt.u32.u64 %0, t; }" : "=r"(a) : "l"(p));
    return a;
}
__device__ __forceinline__ void ldm_x4(uint32_t& r0, uint32_t& r1, uint32_t& r2, uint32_t& r3, uint32_t a) {
    asm volatile("ldmatrix.sync.aligned.m8n8.x4.shared.b16 {%0,%1,%2,%3}, [%4];"
                 : "=r"(r0), "=r"(r1), "=r"(r2), "=r"(r3) : "r"(a));
}
__device__ __forceinline__ void ldm_x2(uint32_t& r0, uint32_t& r1, uint32_t a) {
    asm volatile("ldmatrix.sync.aligned.m8n8.x2.shared.b16 {%0,%1}, [%2];"
                 : "=r"(r0), "=r"(r1) : "r"(a));
}
__device__ __forceinline__ void ldm_x2t(uint32_t& r0, uint32_t& r1, uint32_t a) {
    asm volatile("ldmatrix.sync.aligned.m8n8.x2.trans.shared.b16 {%0,%1}, [%2];"
                 : "=r"(r0), "=r"(r1) : "r"(a));
}
__device__ __forceinline__ void mma16816(float* d, const uint32_t* a, const uint32_t* b) {
    asm volatile("mma.sync.aligned.m16n8k16.row.col.f32.bf16.bf16.f32 "
                 "{%0,%1,%2,%3},{%4,%5,%6,%7},{%8,%9},{%0,%1,%2,%3};"
                 : "+f"(d[0]), "+f"(d[1]), "+f"(d[2]), "+f"(d[3])
                 : "r"(a[0]), "r"(a[1]), "r"(a[2]), "r"(a[3]), "r"(b[0]), "r"(b[1]));
}
// split v = hi + lo (bf16 each); pack two lanes into one b32 (x -> low half)
__device__ __forceinline__ void split2(float x, float y, uint32_t& hi, uint32_t& lo) {
    __nv_bfloat16 hx = __float2bfloat16_rn(x);
    __nv_bfloat16 hy = __float2bfloat16_rn(y);
    __nv_bfloat16 lx = __float2bfloat16_rn(x - __bfloat162float(hx));
    __nv_bfloat16 ly = __float2bfloat16_rn(y - __bfloat162float(hy));
    hi = ((uint32_t)__bfloat16_as_ushort(hy) << 16) | __bfloat16_as_ushort(hx);
    lo = ((uint32_t)__bfloat16_as_ushort(ly) << 16) | __bfloat16_as_ushort(lx);
}

// ---------------------------------------------------------------------------
__global__ void init_counts_kernel() {
    if (threadIdx.x < NE) g_counts[threadIdx.x] = 0;
}

__global__ void router_kernel(const float* __restrict__ x,
                              const float* __restrict__ rw) {
    int warp = (blockIdx.x * blockDim.x + threadIdx.x) >> 5;
    int lane = threadIdx.x & 31;
    if (warp >= NTOK) return;
    const float* xr = x + (size_t)warp * DIM;
    float best = -1e30f;
    int bestE = 0;
#pragma unroll
    for (int e = 0; e < NE; e++) {
        const float* wr = rw + e * DIM;
        float p = 0.f;
        for (int k = lane; k < DIM; k += 32) p += xr[k] * wr[k];
#pragma unroll
        for (int o = 16; o; o >>= 1) p += __shfl_xor_sync(0xffffffffu, p, o);
        if (p > best) { best = p; bestE = e; }   // strict > => first-max (jnp.argmax)
    }
    if (lane == 0) {
        int slot = atomicAdd(&g_counts[bestE], 1);
        g_tlist[bestE * NTOK + slot] = warp;
    }
}

// ---------------------------------------------------------------------------
// Gathered grouped GEMM via mma.sync bf16 with 2-way split (3 products).
// D[M=128 tokens, N=128] = A[M,K] @ B^T  with B operand as col-major KxN.
// BTRANS=true : B src elem (k,n) at Bq[k*HDIM + n]  (GEMM1, fc)   -> smem [k][n], ldmatrix.trans
// BTRANS=false: B src elem (n,k) at Bq[n*HDIM + k]  (GEMM2, proj) -> smem [n][k]
template <int KTOT, bool RELU2, bool BTRANS>
__global__ __launch_bounds__(256, 1) void gemm_mma(
    const float* __restrict__ Abase, int astride,
    const float* __restrict__ Bbase,
    float* __restrict__ Obase, int ostride)
{
    constexpr int KT   = KTOT / TK;
    constexpr int ASZ  = 128 * 80;                   // [m][k] bf16, 80B row stride
    constexpr int BSZ  = BTRANS ? 32 * 272 : 128 * 80;
    constexpr int STAGE = 2 * ASZ + 2 * BSZ;         // Ahi,Alo,Bhi,Blo

    const int e = blockIdx.z;
    const int count = g_counts[e];
    const int m0 = blockIdx.y * TM;
    if (m0 >= count) return;
    const int n0 = blockIdx.x * TN;

    extern __shared__ char smem[];
    int* toks = (int*)smem;
    const int tid = threadIdx.x;
    if (tid < TM) {
        int mg = m0 + tid;
        toks[tid] = (mg < count) ? g_tlist[e * NTOK + mg] : -1;
    }
    __syncthreads();

    const uint32_t sb = smem_u32(smem) + 512;        // tiles base (16B aligned)
    const float* Bq = Bbase + (size_t)e * DIM * HDIM;

    // ---- global load pointers (4 slots each) ----
    const float* aptr[4];
#pragma unroll
    for (int it = 0; it < 4; it++) {
        int idx = it * 256 + tid;
        int tok = toks[idx >> 3];
        aptr[it] = (tok >= 0) ? (Abase + (size_t)tok * astride + (idx & 7) * 4) : nullptr;
    }
    const float* bptr[4];
#pragma unroll
    for (int it = 0; it < 4; it++) {
        int idx = it * 256 + tid;
        if (BTRANS) {
            int kk = idx >> 5, n4 = idx & 31;
            bptr[it] = Bq + (size_t)kk * HDIM + n0 + n4 * 4;
        } else {
            int row = idx >> 3, c4 = idx & 7;
            bptr[it] = Bq + (size_t)(n0 + row) * HDIM + c4 * 4;
        }
    }

    // ---- fragment lane addressing (relative to stage base) ----
    const int lane = tid & 31;
    const int warp = tid >> 5;
    const int wm = (warp >> 2) * 64;
    const int wn = (warp & 3) * 32;

    uint32_t a_addr[4];
#pragma unroll
    for (int i = 0; i < 4; i++)
        a_addr[i] = (uint32_t)((wm + i * 16 + (lane & 15)) * 80 + (lane >> 4) * 16);
    uint32_t b_addr[4];
#pragma unroll
    for (int j = 0; j < 4; j++) {
        if (BTRANS)
            b_addr[j] = (uint32_t)((lane & 15) * 272 + (wn + j * 8) * 2);
        else
            b_addr[j] = (uint32_t)((wn + j * 8 + (lane & 7)) * 80 + ((lane >> 3) & 1) * 16);
    }

    float acc[4][4][4];
#pragma unroll
    for (int i = 0; i < 4; i++)
#pragma unroll
        for (int j = 0; j < 4; j++)
#pragma unroll
            for (int c = 0; c < 4; c++) acc[i][j][c] = 0.f;

    float4 ra[4], rb[4];

    // ---- load / store helpers ----
    auto LOADA = [&](int k0) {
#pragma unroll
        for (int it = 0; it < 4; it++)
            ra[it] = aptr[it] ? *(const float4*)(aptr[it] + k0) : make_float4(0.f, 0.f, 0.f, 0.f);
    };
    auto LOADB = [&](int k0) {
#pragma unroll
        for (int it = 0; it < 4; it++) {
            if (BTRANS) rb[it] = *(const float4*)(bptr[it] + (size_t)k0 * HDIM);
            else        rb[it] = *(const float4*)(bptr[it] + k0);
        }
    };
    auto STORE = [&](int s) {
        char* base = smem + 512 + s * STAGE;
#pragma unroll
        for (int it = 0; it < 4; it++) {       // A tile
            int idx = it * 256 + tid;
            int row = idx >> 3, c4 = idx & 7;
            uint32_t h0, l0, h1, l1;
            split2(ra[it].x, ra[it].y, h0, l0);
            split2(ra[it].z, ra[it].w, h1, l1);
            int off = row * 80 + c4 * 8;
            *(uint2*)(base + off)       = make_uint2(h0, h1);
            *(uint2*)(base + ASZ + off) = make_uint2(l0, l1);
        }
        char* bbase = base + 2 * ASZ;
#pragma unroll
        for (int it = 0; it < 4; it++) {       // B tile
            int idx = it * 256 + tid;
            uint32_t h0, l0, h1, l1;
            split2(rb[it].x, rb[it].y, h0, l0);
            split2(rb[it].z, rb[it].w, h1, l1);
            int off;
            if (BTRANS) { int kk = idx >> 5, n4 = idx & 31; off = kk * 272 + n4 * 8; }
            else        { int row = idx >> 3, c4 = idx & 7; off = row * 80 + c4 * 8; }
            *(uint2*)(bbase + off)       = make_uint2(h0, h1);
            *(uint2*)(bbase + BSZ + off) = make_uint2(l0, l1);
        }
    };
    auto COMPUTE = [&](int s) {
        uint32_t ab = sb + s * STAGE;
        uint32_t bb = ab + 2 * ASZ;
#pragma unroll
        for (int sl = 0; sl < 2; sl++) {       // two k16 slices per TK=32
            uint32_t ah[4][4], al[4][4], bh[4][2], bl[4][2];
#pragma unroll
            for (int i = 0; i < 4; i++) {
                uint32_t ad = ab + a_addr[i] + sl * 32;
                ldm_x4(ah[i][0], ah[i][1], ah[i][2], ah[i][3], ad);
                ldm_x4(al[i][0], al[i][1], al[i][2], al[i][3], ad + ASZ);
            }
#pragma unroll
            for (int j = 0; j < 4; j++) {
                uint32_t bd = bb + b_addr[j] + (BTRANS ? sl * (16 * 272) : sl * 32);
                if (BTRANS) {
                    ldm_x2t(bh[j][0], bh[j][1], bd);
                    ldm_x2t(bl[j][0], bl[j][1], bd + BSZ);
                } else {
                    ldm_x2(bh[j][0], bh[j][1], bd);
                    ldm_x2(bl[j][0], bl[j][1], bd + BSZ);
                }
            }
#pragma unroll
            for (int i = 0; i < 4; i++)
#pragma unroll
                for (int j = 0; j < 4; j++) {
                    mma16816(acc[i][j], ah[i], bh[j]);
                    mma16816(acc[i][j], ah[i], bl[j]);
                    mma16816(acc[i][j], al[i], bh[j]);
                }
        }
    };

    // ---- pipelined main loop ----
    LOADA(0); LOADB(0);
    STORE(0);
    __syncthreads();
    for (int kt = 0; kt < KT; kt++) {
        int s = kt & 1;
        if (kt + 1 < KT) { LOADA((kt + 1) * TK); LOADB((kt + 1) * TK); }
        COMPUTE(s);
        if (kt + 1 < KT) {
            __syncthreads();
            STORE(s ^ 1);
            __syncthreads();
        }
    }

    // ---- epilogue ----
#pragma unroll
    for (int i = 0; i < 4; i++) {
        int r0 = wm + i * 16 + (lane >> 2);
        int r1 = r0 + 8;
        int t0 = toks[r0], t1 = toks[r1];
#pragma unroll
        for (int j = 0; j < 4; j++) {
            int col = n0 + wn + j * 8 + (lane & 3) * 2;
            float2 v0 = make_float2(acc[i][j][0], acc[i][j][1]);
            float2 v1 = make_float2(acc[i][j][2], acc[i][j][3]);
            if (RELU2) {
                v0.x = fmaxf(v0.x, 0.f); v0.x *= v0.x;
                v0.y = fmaxf(v0.y, 0.f); v0.y *= v0.y;
                v1.x = fmaxf(v1.x, 0.f); v1.x *= v1.x;
                v1.y = fmaxf(v1.y, 0.f); v1.y *= v1.y;
            }
            if (t0 >= 0) *(float2*)(Obase + (size_t)t0 * ostride + col) = v0;
            if (t1 >= 0) *(float2*)(Obase + (size_t)t1 * ostride + col) = v1;
        }
    }
}

// ---------------------------------------------------------------------------
#define SMEM1 (512 + 2 * (2 * 128 * 80 + 2 * 32 * 272))    // 76288
#define SMEM2 (512 + 2 * (2 * 128 * 80 + 2 * 128 * 80))    // 82432

extern "C" void kernel_launch(void* const* d_in, const int* in_sizes, int n_in,
                              void* d_out, int out_size) {
    const float* x    = (const float*)d_in[0];
    const float* rw   = (const float*)d_in[1];
    const float* fc   = (const float*)d_in[2];
    const float* proj = (const float*)d_in[3];
    float* out = (float*)d_out;

    cudaFuncSetAttribute(gemm_mma<DIM, true, true>,
                         cudaFuncAttributeMaxDynamicSharedMemorySize, SMEM1);
    cudaFuncSetAttribute(gemm_mma<HDIM, false, false>,
                         cudaFuncAttributeMaxDynamicSharedMemorySize, SMEM2);

    init_counts_kernel<<<1, 32>>>();
    router_kernel<<<(NTOK * 32) / 256, 256>>>(x, rw);

    dim3 g1(HDIM / TN, NTOK / TM, NE);   // 32 x 32 x 8
    gemm_mma<DIM, true, true><<<g1, 256, SMEM1>>>(x, DIM, fc, g_h, HDIM);

    dim3 g2(DIM / TN, NTOK / TM, NE);    // 8 x 32 x 8
    gemm_mma<HDIM, false, false><<<g2, 256, SMEM2>>>(g_h, HDIM, proj, out, DIM);
}